// round 12
// baseline (speedup 1.0000x reference)
#include <cuda_runtime.h>
#include <cuda_fp16.h>
#include <math.h>
#include <stdint.h>

// Problem constants (fixed by the reference)
#define NND  50000          // nodes
#define FH   128            // F == H == 128
#define RR   8              // relations
#define EE   800000         // edges
#define KC   1024           // R*H
#define KCONV (KC+FH)       // 1152
#define NCH  9              // 8 relations + root
#define BN_EPS 1e-5f

// ---------------- scratch (device globals: no allocs allowed) ----------------
__device__ __align__(16) float  g_c[NND*FH];         // conv output (pre-BN)
__device__ __align__(16) __half g_hh[NND*FH];        // h as fp16 (layer-1 output)
__device__ __align__(16) __half g_xh[NND*FH];        // x as fp16 (layer-1 A)
__device__ __align__(16) __half g_ht[(size_t)NND*KCONV];  // transformed feats [N][1152] fp16
__device__ int   g_deg[NND];
__device__ int   g_rowptr[NND+1];
__device__ int   g_cursor[NND];
__device__ int   g_tmp[NND];
__device__ int   g_bsum[512];
__device__ int   g_enc[EE];          // CSR payload: src*9 + type, grouped by dst
__device__ float g_colsum[FH];
__device__ float g_colsq[FH];
__device__ float g_coef[2*FH];
__device__ float g_w2o[FH+1];
// fp16 transposed B matrices ([N rows][K=128 cols] K-major)
__device__ __align__(16) __half g_Bc[KCONV*FH];
__device__ __align__(16) __half g_B1[FH*FH];

// ---------------- small helpers ----------------
__device__ __forceinline__ uint32_t smem_u32(const void* p) {
    uint32_t a;
    asm("{ .reg .u64 t; cvta.to.shared.u64 t, %1; cvt.u32.u64 %0, t; }" : "=r"(a) : "l"(p));
    return a;
}
__device__ __forceinline__ void cp_async16(uint32_t dst, const void* src, int sz) {
    asm volatile("cp.async.cg.shared.global [%0], [%1], 16, %2;"
                 :: "r"(dst), "l"(src), "r"(sz) : "memory");
}
#define CP_COMMIT() asm volatile("cp.async.commit_group;" ::: "memory")
#define CP_WAIT0()  asm volatile("cp.async.wait_group 0;" ::: "memory")
#define CP_WAIT1()  asm volatile("cp.async.wait_group 1;" ::: "memory")
__device__ __forceinline__ void mma_f16(float* c, const uint32_t* a, const uint32_t* b) {
    asm volatile("mma.sync.aligned.m16n8k16.row.col.f32.f16.f16.f32 "
        "{%0,%1,%2,%3}, {%4,%5,%6,%7}, {%8,%9}, {%0,%1,%2,%3};"
        : "+f"(c[0]), "+f"(c[1]), "+f"(c[2]), "+f"(c[3])
        : "r"(a[0]), "r"(a[1]), "r"(a[2]), "r"(a[3]), "r"(b[0]), "r"(b[1]));
}
__device__ __forceinline__ float4 h4f4(uint2 v) {
    __half2 a = *reinterpret_cast<__half2*>(&v.x);
    __half2 b = *reinterpret_cast<__half2*>(&v.y);
    float2 fa = __half22float2(a), fb = __half22float2(b);
    return make_float4(fa.x, fa.y, fb.x, fb.y);
}

// ---------------- prep ----------------
__global__ void prepX_k(const float* __restrict__ x) {
    int i = blockIdx.x*blockDim.x + threadIdx.x;
    if (i < NND*FH) g_xh[i] = __float2half_rn(x[i]);
    if (i < FH) { g_colsum[i] = 0.f; g_colsq[i] = 0.f; }   // initial BN-stat zero
}
__global__ void prepB_k(const float* __restrict__ W1, const float* __restrict__ weight,
                        const float* __restrict__ root) {
    int i = blockIdx.x*blockDim.x + threadIdx.x;
    const int totC = KCONV*FH;
    if (i < totC) {
        int n = i / FH, k = i % FH;   // g_Bc[n][k]
        float v;
        if (n < KC) {
            int r = n >> 7, cout = n & 127;
            v = weight[((size_t)r*FH + k)*FH + cout];
        } else {
            v = root[(size_t)k*FH + (n - KC)];
        }
        g_Bc[i] = __float2half_rn(v);
    } else if (i < totC + FH*FH) {
        int j = i - totC;
        int n = j / FH, k = j % FH;
        g_B1[j] = __float2half_rn(W1[(size_t)k*FH + n]);
    }
}

// ---------------- layer-1 GEMM: h = fp16(x @ W1 + b1), 1-term fp16 ----------------
#define ASTRIDE 80
#define ARRB    (128*ASTRIDE)
#define STG2    (2*ARRB)            // A, B
#define SMEM_GEMM (2*STG2)          // 40960

__global__ void __launch_bounds__(256)
mmagemm_k(const __half* __restrict__ Ah, const __half* __restrict__ Bh,
          const float* __restrict__ bias, __half* __restrict__ Hh)
{
    extern __shared__ char sm[];
    uint32_t smb = smem_u32(sm);
    int t = threadIdx.x, lane = t & 31, wid = t >> 5;
    int m0 = blockIdx.x * 128;
    int wm = (wid >> 2) * 64, wn = (wid & 3) * 32;
    int g = lane >> 2, tig = lane & 3;
    const int nsteps = 4;   // K=128, BK=32

    auto load_stage = [&](int s, int slot) {
        int kc = s << 5;
        #pragma unroll
        for (int i = 0; i < 4; i++) {
            int c = t + i*256;
            int arr = c >> 9, row = (c >> 2) & 127, col = c & 3;
            uint32_t dst = smb + slot*STG2 + arr*ARRB + row*ASTRIDE + col*16;
            const __half* src;
            int sz = 16;
            if (arr == 0) {
                int m = m0 + row;
                if (m >= NND) { m = 0; sz = 0; }
                src = Ah + (size_t)m*FH + kc + col*8;
            } else {
                src = Bh + (size_t)row*FH + kc + col*8;
            }
            cp_async16(dst, src, sz);
        }
        CP_COMMIT();
    };

    float acc[4][4][4];
    #pragma unroll
    for (int a = 0; a < 4; a++)
        #pragma unroll
        for (int b = 0; b < 4; b++)
            #pragma unroll
            for (int q = 0; q < 4; q++) acc[a][b][q] = 0.f;

    load_stage(0, 0);
    load_stage(1, 1);

    for (int s = 0; s < nsteps; s++) {
        CP_WAIT1();
        __syncthreads();
        const char* bs = sm + (s & 1)*STG2;
        #pragma unroll
        for (int kk = 0; kk < 2; kk++) {
            int kbyte = kk*32 + tig*4;
            uint32_t ah[4][4], bb[4][2];
            #pragma unroll
            for (int mi = 0; mi < 4; mi++) {
                const char* p = bs + (wm + mi*16 + g)*ASTRIDE + kbyte;
                ah[mi][0] = *(const uint32_t*)(p);
                ah[mi][1] = *(const uint32_t*)(p + 8*ASTRIDE);
                ah[mi][2] = *(const uint32_t*)(p + 16);
                ah[mi][3] = *(const uint32_t*)(p + 8*ASTRIDE + 16);
            }
            #pragma unroll
            for (int ni = 0; ni < 4; ni++) {
                const char* p = bs + ARRB + (wn + ni*8 + g)*ASTRIDE + kbyte;
                bb[ni][0] = *(const uint32_t*)(p);
                bb[ni][1] = *(const uint32_t*)(p + 16);
            }
            #pragma unroll
            for (int mi = 0; mi < 4; mi++)
                #pragma unroll
                for (int ni = 0; ni < 4; ni++)
                    mma_f16(acc[mi][ni], ah[mi], bb[ni]);
        }
        __syncthreads();
        if (s + 2 < nsteps) load_stage(s + 2, s & 1);
        else CP_COMMIT();
    }
    CP_WAIT0();

    #pragma unroll
    for (int mi = 0; mi < 4; mi++)
        #pragma unroll
        for (int ni = 0; ni < 4; ni++) {
            int n = wn + ni*8 + tig*2;
            float b0 = bias[n], b1 = bias[n+1];
            #pragma unroll
            for (int h2 = 0; h2 < 2; h2++) {
                int m = m0 + wm + mi*16 + g + h2*8;
                if (m < NND) {
                    __half2 hv;
                    hv.x = __float2half_rn(acc[mi][ni][2*h2]   + b0);
                    hv.y = __float2half_rn(acc[mi][ni][2*h2+1] + b1);
                    *(uint32_t*)(Hh + (size_t)m*FH + n) = *reinterpret_cast<uint32_t*>(&hv);
                }
            }
        }
}

// ---------------- conv transform GEMM: persistent-A (BM=64), B double-buffered ----------------
// Grid = 782 blocks. Each block: A tile (64 rows) loaded/computed ONCE, then loops
// the 9 N-chunks; B(c+2) prefetches under chunk c's MMAs. 2 blocks/SM.
// mode 0: A from g_hh (cp.async).  mode 1: A = fp16(relu(c*sc+sh)) in-register.
#define GROWB 272
#define GARRB (128*GROWB)           // B chunk: 34816
#define GA_BYTES (64*GROWB)         // A tile: 17408
#define SM_B0 GA_BYTES
#define SM_B1 (GA_BYTES + GARRB)
#define SMEM_G (GA_BYTES + 2*GARRB) // 87040 -> 2 blocks/SM

__global__ void __launch_bounds__(256, 2)
gemmT_k(int mode)
{
    extern __shared__ char sm[];
    uint32_t smb = smem_u32(sm);
    int t = threadIdx.x, lane = t & 31, wid = t >> 5;
    int m0 = blockIdx.x * 64;
    int g = lane >> 2, tig = lane & 3;
    int wm = (wid >> 2) * 32, wn = (wid & 3) * 32;   // warp tile 32x32 over 64x128

    auto loadB = [&](int c, int buf) {      // 32 KB: chunk c of g_Bc
        int n0 = c * 128;
        #pragma unroll
        for (int j = 0; j < 8; j++) {
            int q = t + j*256, row = q >> 4, col = q & 15;
            cp_async16(smb + GA_BYTES + buf*GARRB + row*GROWB + col*16,
                       g_Bc + (size_t)(n0 + row)*FH + col*8, 16);
        }
        CP_COMMIT();
    };

    if (mode == 0) {
        // A tile via cp.async: 64 rows x 16 chunks -> 4 per thread (joins B0's group)
        #pragma unroll
        for (int j = 0; j < 4; j++) {
            int c = t + j*256;
            int row = c >> 4, col = c & 15;
            int m = m0 + row, sz = 16;
            if (m >= NND) { m = 0; sz = 0; }
            cp_async16(smb + row*GROWB + col*16, g_hh + (size_t)m*FH + col*8, sz);
        }
        loadB(0, 0);    // commit closes A + B0 as one group
        loadB(1, 1);
    } else {
        loadB(0, 0);
        loadB(1, 1);
        // fused BN+ReLU A (fp16), computed ONCE (overlaps in-flight B): 8 float4/thread
        #pragma unroll
        for (int j = 0; j < 8; j++) {
            int q = t + j*256;
            int row = q >> 5, col4 = q & 31;
            int m = m0 + row;
            float4 v = make_float4(0.f, 0.f, 0.f, 0.f);
            if (m < NND) v = *((const float4*)(g_c + (size_t)m*FH) + col4);
            int cb = col4*4;
            v.x = fmaxf(v.x * g_coef[cb+0] + g_coef[FH+cb+0], 0.f);
            v.y = fmaxf(v.y * g_coef[cb+1] + g_coef[FH+cb+1], 0.f);
            v.z = fmaxf(v.z * g_coef[cb+2] + g_coef[FH+cb+2], 0.f);
            v.w = fmaxf(v.w * g_coef[cb+3] + g_coef[FH+cb+3], 0.f);
            __half2 h0, h1;
            h0.x = __float2half_rn(v.x); h0.y = __float2half_rn(v.y);
            h1.x = __float2half_rn(v.z); h1.y = __float2half_rn(v.w);
            uint2 hv;
            hv.x = *reinterpret_cast<uint32_t*>(&h0);
            hv.y = *reinterpret_cast<uint32_t*>(&h1);
            *(uint2*)(sm + row*GROWB + col4*8) = hv;
        }
    }

    for (int c = 0; c < NCH; c++) {
        if (c == NCH - 1) CP_WAIT0(); else CP_WAIT1();   // chunk c (+A at c=0) resident
        __syncthreads();

        float acc[2][4][4];
        #pragma unroll
        for (int a = 0; a < 2; a++)
            #pragma unroll
            for (int b = 0; b < 4; b++)
                #pragma unroll
                for (int q = 0; q < 4; q++) acc[a][b][q] = 0.f;

        const char* bbuf = sm + GA_BYTES + (c & 1)*GARRB;
        #pragma unroll
        for (int kk = 0; kk < 8; kk++) {
            int kbyte = kk*32 + tig*4;
            uint32_t ah[2][4], bb[4][2];
            #pragma unroll
            for (int mi = 0; mi < 2; mi++) {
                const char* p = sm + (wm + mi*16 + g)*GROWB + kbyte;
                ah[mi][0] = *(const uint32_t*)(p);
                ah[mi][1] = *(const uint32_t*)(p + 8*GROWB);
                ah[mi][2] = *(const uint32_t*)(p + 16);
                ah[mi][3] = *(const uint32_t*)(p + 8*GROWB + 16);
            }
            #pragma unroll
            for (int ni = 0; ni < 4; ni++) {
                const char* p = bbuf + (wn + ni*8 + g)*GROWB + kbyte;
                bb[ni][0] = *(const uint32_t*)(p);
                bb[ni][1] = *(const uint32_t*)(p + 16);
            }
            #pragma unroll
            for (int mi = 0; mi < 2; mi++)
                #pragma unroll
                for (int ni = 0; ni < 4; ni++)
                    mma_f16(acc[mi][ni], ah[mi], bb[ni]);
        }

        // store chunk c results (fp16) straight to g_ht
        int n0 = c * 128;
        #pragma unroll
        for (int mi = 0; mi < 2; mi++)
            #pragma unroll
            for (int h2 = 0; h2 < 2; h2++) {
                int m = m0 + wm + mi*16 + g + h2*8;
                if (m < NND) {
                    #pragma unroll
                    for (int ni = 0; ni < 4; ni++) {
                        int n = wn + ni*8 + tig*2;
                        __half2 hv;
                        hv.x = __float2half_rn(acc[mi][ni][2*h2]);
                        hv.y = __float2half_rn(acc[mi][ni][2*h2+1]);
                        *(uint32_t*)(g_ht + (size_t)m*KCONV + n0 + n) =
                            *reinterpret_cast<uint32_t*>(&hv);
                    }
                }
            }

        __syncthreads();                       // all warps done with B buffer c&1
        if (c + 2 < NCH) loadB(c + 2, c & 1);  // refill for chunk c+2
        else CP_COMMIT();                      // keep wait-group accounting uniform
    }
}

// ---------------- CSR build (dst-keyed) ----------------
__global__ void zero_deg_k() {
    int i = blockIdx.x*blockDim.x + threadIdx.x;
    if (i < NND) g_deg[i] = 0;
}
__global__ void hist_k(const int* __restrict__ dst) {
    int e = blockIdx.x*blockDim.x + threadIdx.x;
    if (e < EE) atomicAdd(&g_deg[dst[e]], 1);
}
__global__ void scan1_k() {
    __shared__ int s[1024];
    int t = threadIdx.x;
    int i = blockIdx.x*1024 + t;
    int v = (i < NND) ? g_deg[i] : 0;
    s[t] = v; __syncthreads();
    for (int off = 1; off < 1024; off <<= 1) {
        int x = (t >= off) ? s[t-off] : 0;
        __syncthreads(); s[t] += x; __syncthreads();
    }
    if (i < NND) g_tmp[i] = s[t];
    if (t == 1023) g_bsum[blockIdx.x] = s[t];
}
__global__ void scan2_k(int nb) {
    __shared__ int s[512];
    int t = threadIdx.x;
    s[t] = (t < nb) ? g_bsum[t] : 0; __syncthreads();
    for (int off = 1; off < 512; off <<= 1) {
        int x = (t >= off) ? s[t-off] : 0;
        __syncthreads(); s[t] += x; __syncthreads();
    }
    if (t < nb) g_bsum[t] = s[t];
}
__global__ void scan3_k() {
    int i = blockIdx.x*blockDim.x + threadIdx.x;
    if (i < NND) {
        int b = i >> 10;
        int incl = g_tmp[i] + (b > 0 ? g_bsum[b-1] : 0);
        g_rowptr[i+1] = incl;
        g_cursor[i]   = incl - g_deg[i];
        if (i == 0) g_rowptr[0] = 0;
    }
}
__global__ void scatter_k(const int* __restrict__ src, const int* __restrict__ dst,
                          const int* __restrict__ et) {
    int e = blockIdx.x*blockDim.x + threadIdx.x;
    if (e < EE) {
        int pos = atomicAdd(&g_cursor[dst[e]], 1);
        g_enc[pos] = src[e]*NCH + et[e];
    }
}

// ---------------- gather + bias + fused BN stats ----------------
__global__ void __launch_bounds__(256)
gatherT_k(const float* __restrict__ bias) {
    __shared__ float ss[FH], sq[FH];
    int t = threadIdx.x, lane = t & 31;
    if (t < FH) { ss[t] = 0.f; sq[t] = 0.f; }
    __syncthreads();

    int w = (blockIdx.x*blockDim.x + t) >> 5;   // one warp per node
    if (w < NND) {
        int beg = g_rowptr[w], end = g_rowptr[w+1];
        const uint2* htp = (const uint2*)g_ht;

        float4 acc = h4f4(htp[(size_t)(w*NCH + 8)*32 + lane]);  // root/self
        int e = beg;
        for (; e + 4 <= end; e += 4) {
            int e0 = g_enc[e], e1 = g_enc[e+1], e2 = g_enc[e+2], e3 = g_enc[e+3];
            float4 f0 = h4f4(htp[(size_t)e0*32 + lane]);
            float4 f1 = h4f4(htp[(size_t)e1*32 + lane]);
            float4 f2 = h4f4(htp[(size_t)e2*32 + lane]);
            float4 f3 = h4f4(htp[(size_t)e3*32 + lane]);
            acc.x += (f0.x + f1.x) + (f2.x + f3.x);
            acc.y += (f0.y + f1.y) + (f2.y + f3.y);
            acc.z += (f0.z + f1.z) + (f2.z + f3.z);
            acc.w += (f0.w + f1.w) + (f2.w + f3.w);
        }
        for (; e < end; e++) {
            float4 f = h4f4(htp[(size_t)g_enc[e]*32 + lane]);
            acc.x += f.x; acc.y += f.y; acc.z += f.z; acc.w += f.w;
        }
        float4 b = *((const float4*)bias + lane);
        acc.x += b.x; acc.y += b.y; acc.z += b.z; acc.w += b.w;
        *((float4*)(g_c + (size_t)w*FH) + lane) = acc;

        int cb = lane*4;
        atomicAdd(&ss[cb+0], acc.x); atomicAdd(&sq[cb+0], acc.x*acc.x);
        atomicAdd(&ss[cb+1], acc.y); atomicAdd(&sq[cb+1], acc.y*acc.y);
        atomicAdd(&ss[cb+2], acc.z); atomicAdd(&sq[cb+2], acc.z*acc.z);
        atomicAdd(&ss[cb+3], acc.w); atomicAdd(&sq[cb+3], acc.w*acc.w);
    }
    __syncthreads();
    if (t < FH) {
        atomicAdd(&g_colsum[t], ss[t]);
        atomicAdd(&g_colsq[t],  sq[t]);
    }
}

// ---------------- BN coef (reads stats, then resets them for the next layer) ----------------
__global__ void bncoef_k(const float* __restrict__ gamma, const float* __restrict__ beta) {
    int c = threadIdx.x;
    float mu  = g_colsum[c] / (float)NND;
    float var = g_colsq[c] / (float)NND - mu*mu;
    float sc  = gamma[c] * rsqrtf(var + BN_EPS);
    g_coef[c]      = sc;
    g_coef[FH + c] = beta[c] - mu * sc;
    g_colsum[c] = 0.f;
    g_colsq[c]  = 0.f;
}

// ---------------- head ----------------
__global__ void w2o_k(const float* __restrict__ W2, const float* __restrict__ b2,
                      const float* __restrict__ Wo, const float* __restrict__ bo) {
    int c = threadIdx.x;
    float s = 0.f;
    for (int j = 0; j < FH; j++) s += W2[c*FH + j] * Wo[j];
    g_w2o[c] = s;
    if (c == 0) {
        float b = bo[0];
        for (int j = 0; j < FH; j++) b += b2[j] * Wo[j];
        g_w2o[FH] = b;
    }
}
__global__ void head_k(float* __restrict__ out) {
    int w    = (blockIdx.x*blockDim.x + threadIdx.x) >> 5;
    int lane = threadIdx.x & 31;
    if (w >= NND) return;
    float4 v  = *((const float4*)(g_c + (size_t)w*FH) + lane);
    int cb = lane*4;
    v.x = fmaxf(v.x * g_coef[cb+0] + g_coef[FH+cb+0], 0.f);
    v.y = fmaxf(v.y * g_coef[cb+1] + g_coef[FH+cb+1], 0.f);
    v.z = fmaxf(v.z * g_coef[cb+2] + g_coef[FH+cb+2], 0.f);
    v.w = fmaxf(v.w * g_coef[cb+3] + g_coef[FH+cb+3], 0.f);
    float4 wv = *((const float4*)g_w2o + lane);
    float d = v.x*wv.x + v.y*wv.y + v.z*wv.z + v.w*wv.w;
    #pragma unroll
    for (int off = 16; off; off >>= 1) d += __shfl_down_sync(0xFFFFFFFFu, d, off);
    if (lane == 0) out[w] = 1.f / (1.f + expf(-(d + g_w2o[FH])));
}

// ---------------- launch ----------------
extern "C" void kernel_launch(void* const* d_in, const int* in_sizes, int n_in,
                              void* d_out, int out_size)
{
    const float* x      = (const float*)d_in[0];
    const int*   ei     = (const int*)  d_in[1];
    const int*   et     = (const int*)  d_in[2];
    const float* W1     = (const float*)d_in[3];
    const float* b1     = (const float*)d_in[4];
    const float* weight = (const float*)d_in[5];
    const float* root   = (const float*)d_in[6];
    const float* bias_c = (const float*)d_in[7];
    const float* gamma  = (const float*)d_in[8];
    const float* beta   = (const float*)d_in[9];
    const float* W2     = (const float*)d_in[10];
    const float* b2     = (const float*)d_in[11];
    const float* Wo     = (const float*)d_in[12];
    const float* bo     = (const float*)d_in[13];
    float* out = (float*)d_out;

    __half *xH, *hH, *B1P;
    cudaGetSymbolAddress((void**)&xH,  g_xh);
    cudaGetSymbolAddress((void**)&hH,  g_hh);
    cudaGetSymbolAddress((void**)&B1P, g_B1);

    cudaFuncSetAttribute(mmagemm_k, cudaFuncAttributeMaxDynamicSharedMemorySize, SMEM_GEMM);
    cudaFuncSetAttribute(gemmT_k,   cudaFuncAttributeMaxDynamicSharedMemorySize, SMEM_G);

    const int T = 256;
    const int nScan1 = (NND + 1023) / 1024;   // 49
    const int mTiles = (NND + 127) / 128;     // 391
    const int mTiles64 = (NND + 63) / 64;     // 782

    // launches ordered so gemmT (layer 1) is our 4th kernel -> captured by ncu -s 5
    prepX_k<<<(NND*FH + T-1)/T, T>>>(x);
    prepB_k<<<(KCONV*FH + FH*FH + T-1)/T, T>>>(W1, weight, root);
    mmagemm_k<<<mTiles, 256, SMEM_GEMM>>>(xH, B1P, b1, hH);
    gemmT_k<<<mTiles64, 256, SMEM_G>>>(0);       // layer-1 transform (persistent-A)

    // CSR build (dst-keyed)
    zero_deg_k<<<(NND + T-1)/T, T>>>();
    hist_k<<<(EE + T-1)/T, T>>>(ei + EE);
    scan1_k<<<nScan1, 1024>>>();
    scan2_k<<<1, 512>>>(nScan1);
    scan3_k<<<(NND + T-1)/T, T>>>();
    scatter_k<<<(EE + T-1)/T, T>>>(ei, ei + EE, et);

    w2o_k<<<1, FH>>>(W2, b2, Wo, bo);

    // layer 1: gather + stats -> coef (bncoef resets stats)
    gatherT_k<<<(NND*32 + T-1)/T, T>>>(bias_c);
    bncoef_k<<<1, FH>>>(gamma, beta);

    // layer 2: transform (fused BN+ReLU, persistent-A) -> gather + stats -> coef
    gemmT_k<<<mTiles64, 256, SMEM_G>>>(1);
    gatherT_k<<<(NND*32 + T-1)/T, T>>>(bias_c);
    bncoef_k<<<1, FH>>>(gamma, beta);

    // head (fused BN+ReLU + dot + sigmoid)
    head_k<<<(NND*32 + T-1)/T, T>>>(out);
}

// round 14
// speedup vs baseline: 1.0415x; 1.0415x over previous
#include <cuda_runtime.h>
#include <cuda_fp16.h>
#include <math.h>
#include <stdint.h>

// Problem constants (fixed by the reference)
#define NND  50000          // nodes
#define FH   128            // F == H == 128
#define RR   8              // relations
#define EE   800000         // edges
#define KC   1024           // R*H
#define KCONV (KC+FH)       // 1152
#define NCH  9              // 8 relations + root
#define BN_EPS 1e-5f

// ---------------- scratch (device globals: no allocs allowed) ----------------
__device__ __align__(16) float  g_c[NND*FH];         // conv output (pre-BN)
__device__ __align__(16) __half g_xh[NND*FH];        // x as fp16 (layer-1 A)
__device__ __align__(16) __half g_ht[(size_t)NND*KCONV];  // transformed feats [N][1152] fp16
__device__ int   g_deg[NND];
__device__ int   g_rowptr[NND+1];
__device__ int   g_cursor[NND];
__device__ int   g_tmp[NND];
__device__ int   g_bsum[512];
__device__ int   g_enc[EE];          // CSR payload: src*9 + type, grouped by dst
__device__ float g_colsum[FH];
__device__ float g_colsq[FH];
__device__ float g_coef[2*FH];
__device__ float g_w2o[FH+1];
// fp16 transposed B matrices ([N rows][K=128 cols] K-major)
__device__ __align__(16) __half g_Bc[KCONV*FH];      // conv B (weight|root)
__device__ __align__(16) __half g_B1c[KCONV*FH];     // layer-1 folded B = W1 @ Bc^T
__device__ float g_bc1[KCONV];                       // layer-1 folded bias = b1 @ Bc^T

// ---------------- small helpers ----------------
__device__ __forceinline__ uint32_t smem_u32(const void* p) {
    uint32_t a;
    asm("{ .reg .u64 t; cvta.to.shared.u64 t, %1; cvt.u32.u64 %0, t; }" : "=r"(a) : "l"(p));
    return a;
}
__device__ __forceinline__ void cp_async16(uint32_t dst, const void* src, int sz) {
    asm volatile("cp.async.cg.shared.global [%0], [%1], 16, %2;"
                 :: "r"(dst), "l"(src), "r"(sz) : "memory");
}
#define CP_COMMIT() asm volatile("cp.async.commit_group;" ::: "memory")
#define CP_WAIT0()  asm volatile("cp.async.wait_group 0;" ::: "memory")
#define CP_WAIT1()  asm volatile("cp.async.wait_group 1;" ::: "memory")
__device__ __forceinline__ void mma_f16(float* c, const uint32_t* a, const uint32_t* b) {
    asm volatile("mma.sync.aligned.m16n8k16.row.col.f32.f16.f16.f32 "
        "{%0,%1,%2,%3}, {%4,%5,%6,%7}, {%8,%9}, {%0,%1,%2,%3};"
        : "+f"(c[0]), "+f"(c[1]), "+f"(c[2]), "+f"(c[3])
        : "r"(a[0]), "r"(a[1]), "r"(a[2]), "r"(a[3]), "r"(b[0]), "r"(b[1]));
}
__device__ __forceinline__ float4 h4f4(uint2 v) {
    __half2 a = *reinterpret_cast<__half2*>(&v.x);
    __half2 b = *reinterpret_cast<__half2*>(&v.y);
    float2 fa = __half22float2(a), fb = __half22float2(b);
    return make_float4(fa.x, fa.y, fb.x, fb.y);
}

// ---------------- prep ----------------
__global__ void prepX_k(const float* __restrict__ x) {
    int i = blockIdx.x*blockDim.x + threadIdx.x;
    if (i < NND*FH) g_xh[i] = __float2half_rn(x[i]);
    if (i < FH) { g_colsum[i] = 0.f; g_colsq[i] = 0.f; }   // initial BN-stat zero
}
__global__ void prepB_k(const float* __restrict__ weight, const float* __restrict__ root) {
    int i = blockIdx.x*blockDim.x + threadIdx.x;
    if (i < KCONV*FH) {
        int n = i / FH, k = i % FH;   // g_Bc[n][k]
        float v;
        if (n < KC) {
            int r = n >> 7, cout = n & 127;
            v = weight[((size_t)r*FH + k)*FH + cout];
        } else {
            v = root[(size_t)k*FH + (n - KC)];
        }
        g_Bc[i] = __float2half_rn(v);
    }
}
// Fold W1 into conv B: B1c[n][kx] = sum_j W1[kx][j] * Wr(n,j); bc1[n] = sum_j b1[j]*Wr(n,j)
__global__ void prepB1c_k(const float* __restrict__ W1, const float* __restrict__ b1,
                          const float* __restrict__ weight, const float* __restrict__ root) {
    int i = blockIdx.x*blockDim.x + threadIdx.x;   // i = kx*KCONV + n
    if (i >= FH*KCONV) return;
    int kx = i / KCONV, n = i % KCONV;
    const float* wr;
    int stride;
    if (n < KC) {
        int r = n >> 7, cout = n & 127;
        wr = weight + (size_t)r*FH*FH + cout;   // Wr(n,j) = weight[r][j][cout]
        stride = FH;
    } else {
        wr = root + (n - KC);                   // root[j][cout]
        stride = FH;
    }
    float s = 0.f;
    #pragma unroll 8
    for (int j = 0; j < FH; j++) s += W1[(size_t)kx*FH + j] * wr[(size_t)j*stride];
    g_B1c[(size_t)n*FH + kx] = __float2half_rn(s);
    if (kx == 0) {
        float b = 0.f;
        for (int j = 0; j < FH; j++) b += b1[j] * wr[(size_t)j*stride];
        g_bc1[n] = b;
    }
}

// ---------------- conv transform GEMM (1-term fp16, K-split pipelined; R11 shape) ----------------
// ht[M,1152] = A[M,128] @ B^T (fp16 out). Grid (391, 9).
// mode 0: A from g_xh (cp.async), bias bc1 added in epilogue (layer 1: folded x@W1@Bc^T).
// mode 1: A = fp16(relu(c*sc+sh)) in-register (layer 2), no bias.
#define GROWB 272
#define GARR  (128*GROWB)
#define SMEM_G (2*GARR)             // A, B = 69632

__global__ void __launch_bounds__(256, 2)
gemmT_k(int mode, const __half* __restrict__ B, const float* __restrict__ bias1)
{
    extern __shared__ char sm[];
    uint32_t smb = smem_u32(sm);
    int t = threadIdx.x, lane = t & 31, wid = t >> 5;
    int m0 = blockIdx.x * 128, n0 = blockIdx.y * 128;
    int g = lane >> 2, tig = lane & 3;
    int wm = (wid >> 1) * 32, wn = (wid & 1) * 64;

    if (mode == 0) {
        // group 1: K-half 0 (cols 0-7) of A + B
        #pragma unroll
        for (int j = 0; j < 4; j++) {
            int c = t + j*256, row = c >> 3, col = c & 7;
            int m = m0 + row, sz = 16;
            if (m >= NND) { m = 0; sz = 0; }
            cp_async16(smb + row*GROWB + col*16, g_xh + (size_t)m*FH + col*8, sz);
        }
        #pragma unroll
        for (int j = 0; j < 4; j++) {
            int c = t + j*256, row = c >> 3, col = c & 7;
            cp_async16(smb + GARR + row*GROWB + col*16,
                       B + (size_t)(n0 + row)*FH + col*8, 16);
        }
        CP_COMMIT();
        // group 2: K-half 1 (cols 8-15)
        #pragma unroll
        for (int j = 0; j < 4; j++) {
            int c = t + j*256, row = c >> 3, col = (c & 7) + 8;
            int m = m0 + row, sz = 16;
            if (m >= NND) { m = 0; sz = 0; }
            cp_async16(smb + row*GROWB + col*16, g_xh + (size_t)m*FH + col*8, sz);
        }
        #pragma unroll
        for (int j = 0; j < 4; j++) {
            int c = t + j*256, row = c >> 3, col = (c & 7) + 8;
            cp_async16(smb + GARR + row*GROWB + col*16,
                       B + (size_t)(n0 + row)*FH + col*8, 16);
        }
        CP_COMMIT();
    } else {
        // B halves as two groups; BN+ReLU A (fp16) overlaps in-flight B
        #pragma unroll
        for (int j = 0; j < 4; j++) {
            int c = t + j*256, row = c >> 3, col = c & 7;
            cp_async16(smb + GARR + row*GROWB + col*16,
                       B + (size_t)(n0 + row)*FH + col*8, 16);
        }
        CP_COMMIT();
        #pragma unroll
        for (int j = 0; j < 4; j++) {
            int c = t + j*256, row = c >> 3, col = (c & 7) + 8;
            cp_async16(smb + GARR + row*GROWB + col*16,
                       B + (size_t)(n0 + row)*FH + col*8, 16);
        }
        CP_COMMIT();
        #pragma unroll
        for (int j = 0; j < 16; j++) {
            int q = t + j*256;
            int row = q >> 5, col4 = q & 31;
            int m = m0 + row;
            float4 v = make_float4(0.f, 0.f, 0.f, 0.f);
            if (m < NND) v = *((const float4*)(g_c + (size_t)m*FH) + col4);
            int cb = col4*4;
            v.x = fmaxf(v.x * g_coef[cb+0] + g_coef[FH+cb+0], 0.f);
            v.y = fmaxf(v.y * g_coef[cb+1] + g_coef[FH+cb+1], 0.f);
            v.z = fmaxf(v.z * g_coef[cb+2] + g_coef[FH+cb+2], 0.f);
            v.w = fmaxf(v.w * g_coef[cb+3] + g_coef[FH+cb+3], 0.f);
            __half2 h0, h1;
            h0.x = __float2half_rn(v.x); h0.y = __float2half_rn(v.y);
            h1.x = __float2half_rn(v.z); h1.y = __float2half_rn(v.w);
            uint2 hv;
            hv.x = *reinterpret_cast<uint32_t*>(&h0);
            hv.y = *reinterpret_cast<uint32_t*>(&h1);
            *(uint2*)(sm + row*GROWB + col4*8) = hv;
        }
    }

    float acc[2][8][4];
    #pragma unroll
    for (int a = 0; a < 2; a++)
        #pragma unroll
        for (int b = 0; b < 8; b++)
            #pragma unroll
            for (int q = 0; q < 4; q++) acc[a][b][q] = 0.f;

    auto mma_half = [&](int kk0) {
        #pragma unroll
        for (int kk = 0; kk < 4; kk++) {
            int kbyte = (kk0 + kk)*32 + tig*4;
            uint32_t ah[2][4], bb[8][2];
            #pragma unroll
            for (int mi = 0; mi < 2; mi++) {
                const char* p = sm + (wm + mi*16 + g)*GROWB + kbyte;
                ah[mi][0] = *(const uint32_t*)(p);
                ah[mi][1] = *(const uint32_t*)(p + 8*GROWB);
                ah[mi][2] = *(const uint32_t*)(p + 16);
                ah[mi][3] = *(const uint32_t*)(p + 8*GROWB + 16);
            }
            #pragma unroll
            for (int ni = 0; ni < 8; ni++) {
                const char* p = sm + GARR + (wn + ni*8 + g)*GROWB + kbyte;
                bb[ni][0] = *(const uint32_t*)(p);
                bb[ni][1] = *(const uint32_t*)(p + 16);
            }
            #pragma unroll
            for (int mi = 0; mi < 2; mi++)
                #pragma unroll
                for (int ni = 0; ni < 8; ni++)
                    mma_f16(acc[mi][ni], ah[mi], bb[ni]);
        }
    };

    CP_WAIT1();          // K-half 0 resident (mode1: B-half0 + A done locally)
    __syncthreads();
    mma_half(0);
    CP_WAIT0();          // K-half 1 resident
    __syncthreads();
    mma_half(4);

    #pragma unroll
    for (int mi = 0; mi < 2; mi++)
        #pragma unroll
        for (int h2 = 0; h2 < 2; h2++) {
            int m = m0 + wm + mi*16 + g + h2*8;
            if (m < NND) {
                #pragma unroll
                for (int ni = 0; ni < 8; ni++) {
                    int n = wn + ni*8 + tig*2;
                    float v0 = acc[mi][ni][2*h2];
                    float v1 = acc[mi][ni][2*h2+1];
                    if (bias1) {
                        v0 += bias1[n0 + n];
                        v1 += bias1[n0 + n + 1];
                    }
                    __half2 hv;
                    hv.x = __float2half_rn(v0);
                    hv.y = __float2half_rn(v1);
                    *(uint32_t*)(g_ht + (size_t)m*KCONV + n0 + n) =
                        *reinterpret_cast<uint32_t*>(&hv);
                }
            }
        }
}

// ---------------- CSR build (dst-keyed) ----------------
__global__ void zero_deg_k() {
    int i = blockIdx.x*blockDim.x + threadIdx.x;
    if (i < NND) g_deg[i] = 0;
}
__global__ void hist_k(const int* __restrict__ dst) {
    int e = blockIdx.x*blockDim.x + threadIdx.x;
    if (e < EE) atomicAdd(&g_deg[dst[e]], 1);
}
__global__ void scan1_k() {
    __shared__ int s[1024];
    int t = threadIdx.x;
    int i = blockIdx.x*1024 + t;
    int v = (i < NND) ? g_deg[i] : 0;
    s[t] = v; __syncthreads();
    for (int off = 1; off < 1024; off <<= 1) {
        int x = (t >= off) ? s[t-off] : 0;
        __syncthreads(); s[t] += x; __syncthreads();
    }
    if (i < NND) g_tmp[i] = s[t];
    if (t == 1023) g_bsum[blockIdx.x] = s[t];
}
__global__ void scan2_k(int nb) {
    __shared__ int s[512];
    int t = threadIdx.x;
    s[t] = (t < nb) ? g_bsum[t] : 0; __syncthreads();
    for (int off = 1; off < 512; off <<= 1) {
        int x = (t >= off) ? s[t-off] : 0;
        __syncthreads(); s[t] += x; __syncthreads();
    }
    if (t < nb) g_bsum[t] = s[t];
}
__global__ void scan3_k() {
    int i = blockIdx.x*blockDim.x + threadIdx.x;
    if (i < NND) {
        int b = i >> 10;
        int incl = g_tmp[i] + (b > 0 ? g_bsum[b-1] : 0);
        g_rowptr[i+1] = incl;
        g_cursor[i]   = incl - g_deg[i];
        if (i == 0) g_rowptr[0] = 0;
    }
}
__global__ void scatter_k(const int* __restrict__ src, const int* __restrict__ dst,
                          const int* __restrict__ et) {
    int e = blockIdx.x*blockDim.x + threadIdx.x;
    if (e < EE) {
        int pos = atomicAdd(&g_cursor[dst[e]], 1);
        g_enc[pos] = src[e]*NCH + et[e];
    }
}

// ---------------- gather + bias + fused BN stats ----------------
__global__ void __launch_bounds__(256)
gatherT_k(const float* __restrict__ bias) {
    __shared__ float ss[FH], sq[FH];
    int t = threadIdx.x, lane = t & 31;
    if (t < FH) { ss[t] = 0.f; sq[t] = 0.f; }
    __syncthreads();

    int w = (blockIdx.x*blockDim.x + t) >> 5;   // one warp per node
    if (w < NND) {
        int beg = g_rowptr[w], end = g_rowptr[w+1];
        const uint2* htp = (const uint2*)g_ht;

        float4 acc = h4f4(htp[(size_t)(w*NCH + 8)*32 + lane]);  // root/self
        int e = beg;
        for (; e + 4 <= end; e += 4) {
            int e0 = g_enc[e], e1 = g_enc[e+1], e2 = g_enc[e+2], e3 = g_enc[e+3];
            float4 f0 = h4f4(htp[(size_t)e0*32 + lane]);
            float4 f1 = h4f4(htp[(size_t)e1*32 + lane]);
            float4 f2 = h4f4(htp[(size_t)e2*32 + lane]);
            float4 f3 = h4f4(htp[(size_t)e3*32 + lane]);
            acc.x += (f0.x + f1.x) + (f2.x + f3.x);
            acc.y += (f0.y + f1.y) + (f2.y + f3.y);
            acc.z += (f0.z + f1.z) + (f2.z + f3.z);
            acc.w += (f0.w + f1.w) + (f2.w + f3.w);
        }
        for (; e < end; e++) {
            float4 f = h4f4(htp[(size_t)g_enc[e]*32 + lane]);
            acc.x += f.x; acc.y += f.y; acc.z += f.z; acc.w += f.w;
        }
        float4 b = *((const float4*)bias + lane);
        acc.x += b.x; acc.y += b.y; acc.z += b.z; acc.w += b.w;
        *((float4*)(g_c + (size_t)w*FH) + lane) = acc;

        int cb = lane*4;
        atomicAdd(&ss[cb+0], acc.x); atomicAdd(&sq[cb+0], acc.x*acc.x);
        atomicAdd(&ss[cb+1], acc.y); atomicAdd(&sq[cb+1], acc.y*acc.y);
        atomicAdd(&ss[cb+2], acc.z); atomicAdd(&sq[cb+2], acc.z*acc.z);
        atomicAdd(&ss[cb+3], acc.w); atomicAdd(&sq[cb+3], acc.w*acc.w);
    }
    __syncthreads();
    if (t < FH) {
        atomicAdd(&g_colsum[t], ss[t]);
        atomicAdd(&g_colsq[t],  sq[t]);
    }
}

// ---------------- BN coef (reads stats, then resets them for the next layer) ----------------
__global__ void bncoef_k(const float* __restrict__ gamma, const float* __restrict__ beta) {
    int c = threadIdx.x;
    float mu  = g_colsum[c] / (float)NND;
    float var = g_colsq[c] / (float)NND - mu*mu;
    float sc  = gamma[c] * rsqrtf(var + BN_EPS);
    g_coef[c]      = sc;
    g_coef[FH + c] = beta[c] - mu * sc;
    g_colsum[c] = 0.f;
    g_colsq[c]  = 0.f;
}

// ---------------- head ----------------
__global__ void w2o_k(const float* __restrict__ W2, const float* __restrict__ b2,
                      const float* __restrict__ Wo, const float* __restrict__ bo) {
    int c = threadIdx.x;
    float s = 0.f;
    for (int j = 0; j < FH; j++) s += W2[c*FH + j] * Wo[j];
    g_w2o[c] = s;
    if (c == 0) {
        float b = bo[0];
        for (int j = 0; j < FH; j++) b += b2[j] * Wo[j];
        g_w2o[FH] = b;
    }
}
__global__ void head_k(float* __restrict__ out) {
    int w    = (blockIdx.x*blockDim.x + threadIdx.x) >> 5;
    int lane = threadIdx.x & 31;
    if (w >= NND) return;
    float4 v  = *((const float4*)(g_c + (size_t)w*FH) + lane);
    int cb = lane*4;
    v.x = fmaxf(v.x * g_coef[cb+0] + g_coef[FH+cb+0], 0.f);
    v.y = fmaxf(v.y * g_coef[cb+1] + g_coef[FH+cb+1], 0.f);
    v.z = fmaxf(v.z * g_coef[cb+2] + g_coef[FH+cb+2], 0.f);
    v.w = fmaxf(v.w * g_coef[cb+3] + g_coef[FH+cb+3], 0.f);
    float4 wv = *((const float4*)g_w2o + lane);
    float d = v.x*wv.x + v.y*wv.y + v.z*wv.z + v.w*wv.w;
    #pragma unroll
    for (int off = 16; off; off >>= 1) d += __shfl_down_sync(0xFFFFFFFFu, d, off);
    if (lane == 0) out[w] = 1.f / (1.f + expf(-(d + g_w2o[FH])));
}

// ---------------- launch ----------------
extern "C" void kernel_launch(void* const* d_in, const int* in_sizes, int n_in,
                              void* d_out, int out_size)
{
    const float* x      = (const float*)d_in[0];
    const int*   ei     = (const int*)  d_in[1];
    const int*   et     = (const int*)  d_in[2];
    const float* W1     = (const float*)d_in[3];
    const float* b1     = (const float*)d_in[4];
    const float* weight = (const float*)d_in[5];
    const float* root   = (const float*)d_in[6];
    const float* bias_c = (const float*)d_in[7];
    const float* gamma  = (const float*)d_in[8];
    const float* beta   = (const float*)d_in[9];
    const float* W2     = (const float*)d_in[10];
    const float* b2     = (const float*)d_in[11];
    const float* Wo     = (const float*)d_in[12];
    const float* bo     = (const float*)d_in[13];
    float* out = (float*)d_out;

    __half *BcP, *B1cP;
    float *bc1P;
    cudaGetSymbolAddress((void**)&BcP,  g_Bc);
    cudaGetSymbolAddress((void**)&B1cP, g_B1c);
    cudaGetSymbolAddress((void**)&bc1P, g_bc1);

    cudaFuncSetAttribute(gemmT_k, cudaFuncAttributeMaxDynamicSharedMemorySize, SMEM_G);

    const int T = 256;
    const int nScan1 = (NND + 1023) / 1024;   // 49
    const int mTiles = (NND + 127) / 128;     // 391

    // launches ordered so gemmT (layer 1) is our 4th kernel -> captured by ncu -s 5
    prepX_k<<<(NND*FH + T-1)/T, T>>>(x);
    prepB_k<<<(KCONV*FH + T-1)/T, T>>>(weight, root);
    prepB1c_k<<<(FH*KCONV + T-1)/T, T>>>(W1, b1, weight, root);
    gemmT_k<<<dim3(mTiles, NCH), 256, SMEM_G>>>(0, B1cP, bc1P);   // layer-1 (folded)

    // CSR build (dst-keyed)
    zero_deg_k<<<(NND + T-1)/T, T>>>();
    hist_k<<<(EE + T-1)/T, T>>>(ei + EE);
    scan1_k<<<nScan1, 1024>>>();
    scan2_k<<<1, 512>>>(nScan1);
    scan3_k<<<(NND + T-1)/T, T>>>();
    scatter_k<<<(EE + T-1)/T, T>>>(ei, ei + EE, et);

    w2o_k<<<1, FH>>>(W2, b2, Wo, bo);

    // layer 1: gather + stats -> coef (bncoef resets stats)
    gatherT_k<<<(NND*32 + T-1)/T, T>>>(bias_c);
    bncoef_k<<<1, FH>>>(gamma, beta);

    // layer 2: transform (fused BN+ReLU) -> gather + stats -> coef
    gemmT_k<<<dim3(mTiles, NCH), 256, SMEM_G>>>(1, BcP, nullptr);
    gatherT_k<<<(NND*32 + T-1)/T, T>>>(bias_c);
    bncoef_k<<<1, FH>>>(gamma, beta);

    // head (fused BN+ReLU + dot + sigmoid)
    head_k<<<(NND*32 + T-1)/T, T>>>(out);
}

// round 15
// speedup vs baseline: 1.1061x; 1.0620x over previous
#include <cuda_runtime.h>
#include <cuda_fp16.h>
#include <math.h>
#include <stdint.h>

// Problem constants (fixed by the reference)
#define NND  50000          // nodes
#define FH   128            // F == H == 128
#define RR   8              // relations
#define EE   800000         // edges
#define KC   1024           // R*H
#define KCONV (KC+FH)       // 1152
#define NCH  9              // 8 relations + root
#define BN_EPS 1e-5f

// ---------------- scratch (device globals: no allocs allowed) ----------------
__device__ __align__(16) float  g_c[NND*FH];         // conv output (pre-BN)
__device__ __align__(16) __half g_xh[NND*FH];        // fp16 A operand (x, then relu(bn(c)))
__device__ __align__(16) __half g_ht[(size_t)NND*KCONV];  // transformed feats [N][1152] fp16
__device__ int   g_deg[NND];
__device__ int   g_rowptr[NND+1];
__device__ int   g_cursor[NND];
__device__ int   g_tmp[NND];
__device__ int   g_bsum[512];
__device__ int   g_enc[EE];          // CSR payload: src*9 + type, grouped by dst
__device__ float g_colsum[FH];
__device__ float g_colsq[FH];
__device__ float g_coef[2*FH];
__device__ float g_w2o[FH+1];
// fp16 transposed B matrices ([N rows][K=128 cols] K-major)
__device__ __align__(16) __half g_Bc[KCONV*FH];      // conv B (weight|root)
__device__ __align__(16) __half g_B1c[KCONV*FH];     // layer-1 folded B = W1 @ Bc^T
__device__ float g_bc1[KCONV];                       // layer-1 folded bias = b1 @ Bc^T

// ---------------- small helpers ----------------
__device__ __forceinline__ uint32_t smem_u32(const void* p) {
    uint32_t a;
    asm("{ .reg .u64 t; cvta.to.shared.u64 t, %1; cvt.u32.u64 %0, t; }" : "=r"(a) : "l"(p));
    return a;
}
__device__ __forceinline__ void cp_async16(uint32_t dst, const void* src, int sz) {
    asm volatile("cp.async.cg.shared.global [%0], [%1], 16, %2;"
                 :: "r"(dst), "l"(src), "r"(sz) : "memory");
}
#define CP_COMMIT() asm volatile("cp.async.commit_group;" ::: "memory")
#define CP_WAIT0()  asm volatile("cp.async.wait_group 0;" ::: "memory")
#define CP_WAIT1()  asm volatile("cp.async.wait_group 1;" ::: "memory")
__device__ __forceinline__ void mma_f16(float* c, const uint32_t* a, const uint32_t* b) {
    asm volatile("mma.sync.aligned.m16n8k16.row.col.f32.f16.f16.f32 "
        "{%0,%1,%2,%3}, {%4,%5,%6,%7}, {%8,%9}, {%0,%1,%2,%3};"
        : "+f"(c[0]), "+f"(c[1]), "+f"(c[2]), "+f"(c[3])
        : "r"(a[0]), "r"(a[1]), "r"(a[2]), "r"(a[3]), "r"(b[0]), "r"(b[1]));
}
__device__ __forceinline__ float4 h4f4(uint2 v) {
    __half2 a = *reinterpret_cast<__half2*>(&v.x);
    __half2 b = *reinterpret_cast<__half2*>(&v.y);
    float2 fa = __half22float2(a), fb = __half22float2(b);
    return make_float4(fa.x, fa.y, fb.x, fb.y);
}

// ---------------- prep ----------------
__global__ void prepX_k(const float* __restrict__ x) {
    int i = blockIdx.x*blockDim.x + threadIdx.x;
    if (i < NND*FH) g_xh[i] = __float2half_rn(x[i]);
    if (i < FH) { g_colsum[i] = 0.f; g_colsq[i] = 0.f; }
    if (i < NND) g_deg[i] = 0;                       // merged zero_deg
}
__global__ void prepB_k(const float* __restrict__ weight, const float* __restrict__ root) {
    int i = blockIdx.x*blockDim.x + threadIdx.x;
    if (i < KCONV*FH) {
        int n = i / FH, k = i % FH;   // g_Bc[n][k]
        float v;
        if (n < KC) {
            int r = n >> 7, cout = n & 127;
            v = weight[((size_t)r*FH + k)*FH + cout];
        } else {
            v = root[(size_t)k*FH + (n - KC)];
        }
        g_Bc[i] = __float2half_rn(v);
    }
}
// Fold W1 into conv B: B1c[n][kx] = sum_j W1[kx][j] * Wr(n,j); bc1[n] = sum_j b1[j]*Wr(n,j)
__global__ void prepB1c_k(const float* __restrict__ W1, const float* __restrict__ b1,
                          const float* __restrict__ weight, const float* __restrict__ root) {
    int i = blockIdx.x*blockDim.x + threadIdx.x;   // i = kx*KCONV + n
    if (i >= FH*KCONV) return;
    int kx = i / KCONV, n = i % KCONV;
    const float* wr;
    if (n < KC) {
        int r = n >> 7, cout = n & 127;
        wr = weight + (size_t)r*FH*FH + cout;   // Wr(n,j) = weight[r][j][cout]
    } else {
        wr = root + (n - KC);                   // root[j][cout]
    }
    float s = 0.f;
    #pragma unroll 8
    for (int j = 0; j < FH; j++) s += W1[(size_t)kx*FH + j] * wr[(size_t)j*FH];
    g_B1c[(size_t)n*FH + kx] = __float2half_rn(s);
    if (kx == 0) {
        float b = 0.f;
        for (int j = 0; j < FH; j++) b += b1[j] * wr[(size_t)j*FH];
        g_bc1[n] = b;
    }
}

// ---------------- conv transform GEMM (single path; R11 K-split pipeline) ----------------
// ht[M,1152] = A[M,128] @ B^T + bias1 (fp16 out). Grid (391, 9). Bias preloaded to smem.
#define GROWB 272
#define GARR  (128*GROWB)
#define SM_BIAS (2*GARR)
#define SMEM_G (2*GARR + 512)       // A, B, bias = 70144

__global__ void __launch_bounds__(256, 2)
gemmT_k(const __half* __restrict__ A, const __half* __restrict__ B,
        const float* __restrict__ bias1)
{
    extern __shared__ char sm[];
    uint32_t smb = smem_u32(sm);
    int t = threadIdx.x, lane = t & 31, wid = t >> 5;
    int m0 = blockIdx.x * 128, n0 = blockIdx.y * 128;
    int g = lane >> 2, tig = lane & 3;
    int wm = (wid >> 1) * 32, wn = (wid & 1) * 64;

    // bias preload (branch once per block, not per output)
    if (t < 32) {
        float4 bv = bias1 ? *((const float4*)(bias1 + n0) + t) : make_float4(0.f,0.f,0.f,0.f);
        *((float4*)(sm + SM_BIAS) + t) = bv;
    }

    // group 1: K-half 0 (cols 0-7) of A + B
    #pragma unroll
    for (int j = 0; j < 4; j++) {
        int c = t + j*256, row = c >> 3, col = c & 7;
        int m = m0 + row, sz = 16;
        if (m >= NND) { m = 0; sz = 0; }
        cp_async16(smb + row*GROWB + col*16, A + (size_t)m*FH + col*8, sz);
    }
    #pragma unroll
    for (int j = 0; j < 4; j++) {
        int c = t + j*256, row = c >> 3, col = c & 7;
        cp_async16(smb + GARR + row*GROWB + col*16,
                   B + (size_t)(n0 + row)*FH + col*8, 16);
    }
    CP_COMMIT();
    // group 2: K-half 1 (cols 8-15)
    #pragma unroll
    for (int j = 0; j < 4; j++) {
        int c = t + j*256, row = c >> 3, col = (c & 7) + 8;
        int m = m0 + row, sz = 16;
        if (m >= NND) { m = 0; sz = 0; }
        cp_async16(smb + row*GROWB + col*16, A + (size_t)m*FH + col*8, sz);
    }
    #pragma unroll
    for (int j = 0; j < 4; j++) {
        int c = t + j*256, row = c >> 3, col = (c & 7) + 8;
        cp_async16(smb + GARR + row*GROWB + col*16,
                   B + (size_t)(n0 + row)*FH + col*8, 16);
    }
    CP_COMMIT();

    float acc[2][8][4];
    #pragma unroll
    for (int a = 0; a < 2; a++)
        #pragma unroll
        for (int b = 0; b < 8; b++)
            #pragma unroll
            for (int q = 0; q < 4; q++) acc[a][b][q] = 0.f;

    auto mma_half = [&](int kk0) {
        #pragma unroll
        for (int kk = 0; kk < 4; kk++) {
            int kbyte = (kk0 + kk)*32 + tig*4;
            uint32_t ah[2][4], bb[8][2];
            #pragma unroll
            for (int mi = 0; mi < 2; mi++) {
                const char* p = sm + (wm + mi*16 + g)*GROWB + kbyte;
                ah[mi][0] = *(const uint32_t*)(p);
                ah[mi][1] = *(const uint32_t*)(p + 8*GROWB);
                ah[mi][2] = *(const uint32_t*)(p + 16);
                ah[mi][3] = *(const uint32_t*)(p + 8*GROWB + 16);
            }
            #pragma unroll
            for (int ni = 0; ni < 8; ni++) {
                const char* p = sm + GARR + (wn + ni*8 + g)*GROWB + kbyte;
                bb[ni][0] = *(const uint32_t*)(p);
                bb[ni][1] = *(const uint32_t*)(p + 16);
            }
            #pragma unroll
            for (int mi = 0; mi < 2; mi++)
                #pragma unroll
                for (int ni = 0; ni < 8; ni++)
                    mma_f16(acc[mi][ni], ah[mi], bb[ni]);
        }
    };

    CP_WAIT1();          // K-half 0 resident
    __syncthreads();
    mma_half(0);
    CP_WAIT0();          // K-half 1 resident
    __syncthreads();
    mma_half(4);

    const float* sbias = (const float*)(sm + SM_BIAS);
    #pragma unroll
    for (int mi = 0; mi < 2; mi++)
        #pragma unroll
        for (int h2 = 0; h2 < 2; h2++) {
            int m = m0 + wm + mi*16 + g + h2*8;
            if (m < NND) {
                #pragma unroll
                for (int ni = 0; ni < 8; ni++) {
                    int n = wn + ni*8 + tig*2;
                    __half2 hv;
                    hv.x = __float2half_rn(acc[mi][ni][2*h2]   + sbias[n]);
                    hv.y = __float2half_rn(acc[mi][ni][2*h2+1] + sbias[n+1]);
                    *(uint32_t*)(g_ht + (size_t)m*KCONV + n0 + n) =
                        *reinterpret_cast<uint32_t*>(&hv);
                }
            }
        }
}

// ---------------- BN+ReLU -> fp16 A for layer 2 ----------------
__global__ void bnrelu_k() {
    int i = blockIdx.x*blockDim.x + threadIdx.x;   // float4 index
    const int n4 = NND*FH/4;
    if (i < n4) {
        float4 v = *((const float4*)g_c + i);
        int cb = (i & 31) * 4;
        v.x = fmaxf(v.x * g_coef[cb+0] + g_coef[FH+cb+0], 0.f);
        v.y = fmaxf(v.y * g_coef[cb+1] + g_coef[FH+cb+1], 0.f);
        v.z = fmaxf(v.z * g_coef[cb+2] + g_coef[FH+cb+2], 0.f);
        v.w = fmaxf(v.w * g_coef[cb+3] + g_coef[FH+cb+3], 0.f);
        __half2 h0, h1;
        h0.x = __float2half_rn(v.x); h0.y = __float2half_rn(v.y);
        h1.x = __float2half_rn(v.z); h1.y = __float2half_rn(v.w);
        uint2 hv;
        hv.x = *reinterpret_cast<uint32_t*>(&h0);
        hv.y = *reinterpret_cast<uint32_t*>(&h1);
        *reinterpret_cast<uint2*>(g_xh + (size_t)i*4) = hv;
    }
}

// ---------------- CSR build (dst-keyed) ----------------
__global__ void hist_k(const int* __restrict__ dst) {
    int e = blockIdx.x*blockDim.x + threadIdx.x;
    if (e < EE) atomicAdd(&g_deg[dst[e]], 1);
}
__global__ void scan1_k() {
    __shared__ int s[1024];
    int t = threadIdx.x;
    int i = blockIdx.x*1024 + t;
    int v = (i < NND) ? g_deg[i] : 0;
    s[t] = v; __syncthreads();
    for (int off = 1; off < 1024; off <<= 1) {
        int x = (t >= off) ? s[t-off] : 0;
        __syncthreads(); s[t] += x; __syncthreads();
    }
    if (i < NND) g_tmp[i] = s[t];
    if (t == 1023) g_bsum[blockIdx.x] = s[t];
}
__global__ void scan2_k(int nb) {
    __shared__ int s[512];
    int t = threadIdx.x;
    s[t] = (t < nb) ? g_bsum[t] : 0; __syncthreads();
    for (int off = 1; off < 512; off <<= 1) {
        int x = (t >= off) ? s[t-off] : 0;
        __syncthreads(); s[t] += x; __syncthreads();
    }
    if (t < nb) g_bsum[t] = s[t];
}
__global__ void scan3_k() {
    int i = blockIdx.x*blockDim.x + threadIdx.x;
    if (i < NND) {
        int b = i >> 10;
        int incl = g_tmp[i] + (b > 0 ? g_bsum[b-1] : 0);
        g_rowptr[i+1] = incl;
        g_cursor[i]   = incl - g_deg[i];
        if (i == 0) g_rowptr[0] = 0;
    }
}
__global__ void scatter_k(const int* __restrict__ src, const int* __restrict__ dst,
                          const int* __restrict__ et) {
    int e = blockIdx.x*blockDim.x + threadIdx.x;
    if (e < EE) {
        int pos = atomicAdd(&g_cursor[dst[e]], 1);
        g_enc[pos] = src[e]*NCH + et[e];
    }
}

// ---------------- gather + bias + fused BN stats (MLP-8 edge loop) ----------------
__global__ void __launch_bounds__(256)
gatherT_k(const float* __restrict__ bias) {
    __shared__ float ss[FH], sq[FH];
    int t = threadIdx.x, lane = t & 31;
    if (t < FH) { ss[t] = 0.f; sq[t] = 0.f; }
    __syncthreads();

    int w = (blockIdx.x*blockDim.x + t) >> 5;   // one warp per node
    if (w < NND) {
        int beg = g_rowptr[w], end = g_rowptr[w+1];
        const uint2* htp = (const uint2*)g_ht;

        float4 acc = h4f4(htp[(size_t)(w*NCH + 8)*32 + lane]);  // root/self
        int e = beg;
        for (; e + 8 <= end; e += 8) {
            uint2 v[8];
            #pragma unroll
            for (int q = 0; q < 8; q++) v[q] = htp[(size_t)g_enc[e+q]*32 + lane];
            #pragma unroll
            for (int q = 0; q < 8; q++) {
                float4 f = h4f4(v[q]);
                acc.x += f.x; acc.y += f.y; acc.z += f.z; acc.w += f.w;
            }
        }
        for (; e < end; e++) {
            float4 f = h4f4(htp[(size_t)g_enc[e]*32 + lane]);
            acc.x += f.x; acc.y += f.y; acc.z += f.z; acc.w += f.w;
        }
        float4 b = *((const float4*)bias + lane);
        acc.x += b.x; acc.y += b.y; acc.z += b.z; acc.w += b.w;
        *((float4*)(g_c + (size_t)w*FH) + lane) = acc;

        int cb = lane*4;
        atomicAdd(&ss[cb+0], acc.x); atomicAdd(&sq[cb+0], acc.x*acc.x);
        atomicAdd(&ss[cb+1], acc.y); atomicAdd(&sq[cb+1], acc.y*acc.y);
        atomicAdd(&ss[cb+2], acc.z); atomicAdd(&sq[cb+2], acc.z*acc.z);
        atomicAdd(&ss[cb+3], acc.w); atomicAdd(&sq[cb+3], acc.w*acc.w);
    }
    __syncthreads();
    if (t < FH) {
        atomicAdd(&g_colsum[t], ss[t]);
        atomicAdd(&g_colsq[t],  sq[t]);
    }
}

// ---------------- BN coef (reads stats, then resets them for the next layer) ----------------
__global__ void bncoef_k(const float* __restrict__ gamma, const float* __restrict__ beta) {
    int c = threadIdx.x;
    float mu  = g_colsum[c] / (float)NND;
    float var = g_colsq[c] / (float)NND - mu*mu;
    float sc  = gamma[c] * rsqrtf(var + BN_EPS);
    g_coef[c]      = sc;
    g_coef[FH + c] = beta[c] - mu * sc;
    g_colsum[c] = 0.f;
    g_colsq[c]  = 0.f;
}

// ---------------- head ----------------
__global__ void w2o_k(const float* __restrict__ W2, const float* __restrict__ b2,
                      const float* __restrict__ Wo, const float* __restrict__ bo) {
    int c = threadIdx.x;
    float s = 0.f;
    for (int j = 0; j < FH; j++) s += W2[c*FH + j] * Wo[j];
    g_w2o[c] = s;
    if (c == 0) {
        float b = bo[0];
        for (int j = 0; j < FH; j++) b += b2[j] * Wo[j];
        g_w2o[FH] = b;
    }
}
__global__ void head_k(float* __restrict__ out) {
    int w    = (blockIdx.x*blockDim.x + threadIdx.x) >> 5;
    int lane = threadIdx.x & 31;
    if (w >= NND) return;
    float4 v  = *((const float4*)(g_c + (size_t)w*FH) + lane);
    int cb = lane*4;
    v.x = fmaxf(v.x * g_coef[cb+0] + g_coef[FH+cb+0], 0.f);
    v.y = fmaxf(v.y * g_coef[cb+1] + g_coef[FH+cb+1], 0.f);
    v.z = fmaxf(v.z * g_coef[cb+2] + g_coef[FH+cb+2], 0.f);
    v.w = fmaxf(v.w * g_coef[cb+3] + g_coef[FH+cb+3], 0.f);
    float4 wv = *((const float4*)g_w2o + lane);
    float d = v.x*wv.x + v.y*wv.y + v.z*wv.z + v.w*wv.w;
    #pragma unroll
    for (int off = 16; off; off >>= 1) d += __shfl_down_sync(0xFFFFFFFFu, d, off);
    if (lane == 0) out[w] = 1.f / (1.f + expf(-(d + g_w2o[FH])));
}

// ---------------- launch ----------------
extern "C" void kernel_launch(void* const* d_in, const int* in_sizes, int n_in,
                              void* d_out, int out_size)
{
    const float* x      = (const float*)d_in[0];
    const int*   ei     = (const int*)  d_in[1];
    const int*   et     = (const int*)  d_in[2];
    const float* W1     = (const float*)d_in[3];
    const float* b1     = (const float*)d_in[4];
    const float* weight = (const float*)d_in[5];
    const float* root   = (const float*)d_in[6];
    const float* bias_c = (const float*)d_in[7];
    const float* gamma  = (const float*)d_in[8];
    const float* beta   = (const float*)d_in[9];
    const float* W2     = (const float*)d_in[10];
    const float* b2     = (const float*)d_in[11];
    const float* Wo     = (const float*)d_in[12];
    const float* bo     = (const float*)d_in[13];
    float* out = (float*)d_out;

    __half *xHP, *BcP, *B1cP;
    float *bc1P;
    cudaGetSymbolAddress((void**)&xHP,  g_xh);
    cudaGetSymbolAddress((void**)&BcP,  g_Bc);
    cudaGetSymbolAddress((void**)&B1cP, g_B1c);
    cudaGetSymbolAddress((void**)&bc1P, g_bc1);

    cudaFuncSetAttribute(gemmT_k, cudaFuncAttributeMaxDynamicSharedMemorySize, SMEM_G);

    const int T = 256;
    const int nScan1 = (NND + 1023) / 1024;   // 49
    const int mTiles = (NND + 127) / 128;     // 391

    // launches ordered so gemmT (layer 1) is our 4th kernel -> captured by ncu -s 5
    prepX_k<<<(NND*FH + T-1)/T, T>>>(x);
    prepB_k<<<(KCONV*FH + T-1)/T, T>>>(weight, root);
    prepB1c_k<<<(FH*KCONV + T-1)/T, T>>>(W1, b1, weight, root);
    gemmT_k<<<dim3(mTiles, NCH), 256, SMEM_G>>>(xHP, B1cP, bc1P);   // layer-1 (folded)

    // CSR build (dst-keyed)
    hist_k<<<(EE + T-1)/T, T>>>(ei + EE);
    scan1_k<<<nScan1, 1024>>>();
    scan2_k<<<1, 512>>>(nScan1);
    scan3_k<<<(NND + T-1)/T, T>>>();
    scatter_k<<<(EE + T-1)/T, T>>>(ei, ei + EE, et);

    w2o_k<<<1, FH>>>(W2, b2, Wo, bo);

    // layer 1: gather + stats -> coef (bncoef resets stats)
    gatherT_k<<<(NND*32 + T-1)/T, T>>>(bias_c);
    bncoef_k<<<1, FH>>>(gamma, beta);

    // layer 2: BN+ReLU -> fp16 A, then transform -> gather + stats -> coef
    bnrelu_k<<<(NND*FH/4 + T-1)/T, T>>>();
    gemmT_k<<<dim3(mTiles, NCH), 256, SMEM_G>>>(xHP, BcP, nullptr);
    gatherT_k<<<(NND*32 + T-1)/T, T>>>(bias_c);
    bncoef_k<<<1, FH>>>(gamma, beta);

    // head (fused BN+ReLU + dot + sigmoid)
    head_k<<<(NND*32 + T-1)/T, T>>>(out);
}

// round 17
// speedup vs baseline: 1.1178x; 1.0107x over previous
#include <cuda_runtime.h>
#include <cuda_fp16.h>
#include <math.h>
#include <stdint.h>

// Problem constants (fixed by the reference)
#define NND  50000          // nodes
#define FH   128            // F == H == 128
#define RR   8              // relations
#define EE   800000         // edges
#define KC   1024           // R*H
#define KCONV (KC+FH)       // 1152
#define NCH  9              // 8 relations + root
#define BN_EPS 1e-5f

// ---------------- scratch (device globals: no allocs allowed) ----------------
__device__ __align__(16) float  g_c[NND*FH];         // conv output (pre-BN)
__device__ __align__(16) __half g_xh[NND*FH];        // fp16 A operand (x, then relu(bn(c)))
__device__ __align__(16) __half g_ht[(size_t)NND*KCONV];  // transformed feats [N][1152] fp16
__device__ int   g_deg[NND];
__device__ int   g_rowptr[NND+1];
__device__ int   g_cursor[NND];
__device__ int   g_tmp[NND];
__device__ int   g_bsum[512];
__device__ int   g_enc[EE];          // CSR payload: src*9 + type, grouped by dst
__device__ float g_colsum[FH];
__device__ float g_colsq[FH];
__device__ float g_coef[2*FH];
__device__ float g_w2o[FH+1];
// fp16 transposed B matrices ([N rows][K=128 cols] K-major)
__device__ __align__(16) __half g_Bc[KCONV*FH];      // conv B (weight|root)
__device__ __align__(16) __half g_B1c[KCONV*FH];     // layer-1 folded B = W1 @ Bc^T
__device__ float g_bc1[KCONV];                       // layer-1 folded bias = b1 @ Bc^T

// ---------------- small helpers ----------------
__device__ __forceinline__ uint32_t smem_u32(const void* p) {
    uint32_t a;
    asm("{ .reg .u64 t; cvta.to.shared.u64 t, %1; cvt.u32.u64 %0, t; }" : "=r"(a) : "l"(p));
    return a;
}
__device__ __forceinline__ void cp_async16(uint32_t dst, const void* src, int sz) {
    asm volatile("cp.async.cg.shared.global [%0], [%1], 16, %2;"
                 :: "r"(dst), "l"(src), "r"(sz) : "memory");
}
#define CP_COMMIT() asm volatile("cp.async.commit_group;" ::: "memory")
#define CP_WAIT0()  asm volatile("cp.async.wait_group 0;" ::: "memory")
#define CP_WAIT1()  asm volatile("cp.async.wait_group 1;" ::: "memory")
__device__ __forceinline__ void mma_f16(float* c, const uint32_t* a, const uint32_t* b) {
    asm volatile("mma.sync.aligned.m16n8k16.row.col.f32.f16.f16.f32 "
        "{%0,%1,%2,%3}, {%4,%5,%6,%7}, {%8,%9}, {%0,%1,%2,%3};"
        : "+f"(c[0]), "+f"(c[1]), "+f"(c[2]), "+f"(c[3])
        : "r"(a[0]), "r"(a[1]), "r"(a[2]), "r"(a[3]), "r"(b[0]), "r"(b[1]));
}
__device__ __forceinline__ float4 h4f4(uint2 v) {
    __half2 a = *reinterpret_cast<__half2*>(&v.x);
    __half2 b = *reinterpret_cast<__half2*>(&v.y);
    float2 fa = __half22float2(a), fb = __half22float2(b);
    return make_float4(fa.x, fa.y, fb.x, fb.y);
}

// ---------------- prep ----------------
__global__ void prepX_k(const float* __restrict__ x) {
    int i = blockIdx.x*blockDim.x + threadIdx.x;
    if (i < NND*FH) g_xh[i] = __float2half_rn(x[i]);
    if (i < FH) { g_colsum[i] = 0.f; g_colsq[i] = 0.f; }
    if (i < NND) g_deg[i] = 0;                       // merged zero_deg
}
__global__ void prepB_k(const float* __restrict__ weight, const float* __restrict__ root) {
    int i = blockIdx.x*blockDim.x + threadIdx.x;
    if (i < KCONV*FH) {
        int n = i / FH, k = i % FH;   // g_Bc[n][k]
        float v;
        if (n < KC) {
            int r = n >> 7, cout = n & 127;
            v = weight[((size_t)r*FH + k)*FH + cout];
        } else {
            v = root[(size_t)k*FH + (n - KC)];
        }
        g_Bc[i] = __float2half_rn(v);
    }
}
// Fold W1 into conv B: B1c[n][kx] = sum_j W1[kx][j] * Wr(n,j); bc1[n] = sum_j b1[j]*Wr(n,j)
__global__ void prepB1c_k(const float* __restrict__ W1, const float* __restrict__ b1,
                          const float* __restrict__ weight, const float* __restrict__ root) {
    int i = blockIdx.x*blockDim.x + threadIdx.x;   // i = kx*KCONV + n
    if (i >= FH*KCONV) return;
    int kx = i / KCONV, n = i % KCONV;
    const float* wr;
    if (n < KC) {
        int r = n >> 7, cout = n & 127;
        wr = weight + (size_t)r*FH*FH + cout;   // Wr(n,j) = weight[r][j][cout]
    } else {
        wr = root + (n - KC);                   // root[j][cout]
    }
    float s = 0.f;
    #pragma unroll 8
    for (int j = 0; j < FH; j++) s += W1[(size_t)kx*FH + j] * wr[(size_t)j*FH];
    g_B1c[(size_t)n*FH + kx] = __float2half_rn(s);
    if (kx == 0) {
        float b = 0.f;
        for (int j = 0; j < FH; j++) b += b1[j] * wr[(size_t)j*FH];
        g_bc1[n] = b;
    }
}

// ---------------- conv transform GEMM (128 threads, 64x64 warp tiles) ----------------
// ht[M,1152] = A[M,128] @ B^T + bias1 (fp16 out). Grid (391, 9).
// 4 warps each own a 64x64 C sub-tile: fragment loads/MMA drop 1.5 -> 1.0.
// K-split two-commit-group pipeline (R11/R15 measured-best load schedule).
#define GROWB 272
#define GARR  (128*GROWB)
#define SM_BIAS (2*GARR)
#define SMEM_G (2*GARR + 512)       // A, B, bias = 70144

__global__ void __launch_bounds__(128, 2)
gemmT_k(const __half* __restrict__ A, const __half* __restrict__ B,
        const float* __restrict__ bias1)
{
    extern __shared__ char sm[];
    uint32_t smb = smem_u32(sm);
    int t = threadIdx.x, lane = t & 31, wid = t >> 5;
    int m0 = blockIdx.x * 128, n0 = blockIdx.y * 128;
    int g = lane >> 2, tig = lane & 3;
    int wm = (wid >> 1) * 64, wn = (wid & 1) * 64;

    // bias preload (branch once per block, not per output)
    if (t < 32) {
        float4 bv = bias1 ? *((const float4*)(bias1 + n0) + t) : make_float4(0.f,0.f,0.f,0.f);
        *((float4*)(sm + SM_BIAS) + t) = bv;
    }

    // group 1: K-half 0 (cols 0-7) of A + B   (128 threads -> 8 chunks each)
    #pragma unroll
    for (int j = 0; j < 8; j++) {
        int c = t + j*128, row = c >> 3, col = c & 7;
        int m = m0 + row, sz = 16;
        if (m >= NND) { m = 0; sz = 0; }
        cp_async16(smb + row*GROWB + col*16, A + (size_t)m*FH + col*8, sz);
    }
    #pragma unroll
    for (int j = 0; j < 8; j++) {
        int c = t + j*128, row = c >> 3, col = c & 7;
        cp_async16(smb + GARR + row*GROWB + col*16,
                   B + (size_t)(n0 + row)*FH + col*8, 16);
    }
    CP_COMMIT();
    // group 2: K-half 1 (cols 8-15)
    #pragma unroll
    for (int j = 0; j < 8; j++) {
        int c = t + j*128, row = c >> 3, col = (c & 7) + 8;
        int m = m0 + row, sz = 16;
        if (m >= NND) { m = 0; sz = 0; }
        cp_async16(smb + row*GROWB + col*16, A + (size_t)m*FH + col*8, sz);
    }
    #pragma unroll
    for (int j = 0; j < 8; j++) {
        int c = t + j*128, row = c >> 3, col = (c & 7) + 8;
        cp_async16(smb + GARR + row*GROWB + col*16,
                   B + (size_t)(n0 + row)*FH + col*8, 16);
    }
    CP_COMMIT();

    float acc[4][8][4];
    #pragma unroll
    for (int a = 0; a < 4; a++)
        #pragma unroll
        for (int b = 0; b < 8; b++)
            #pragma unroll
            for (int q = 0; q < 4; q++) acc[a][b][q] = 0.f;

    auto mma_half = [&](int kk0) {
        #pragma unroll
        for (int kk = 0; kk < 4; kk++) {
            int kbyte = (kk0 + kk)*32 + tig*4;
            uint32_t ah[4][4], bb[8][2];
            #pragma unroll
            for (int mi = 0; mi < 4; mi++) {
                const char* p = sm + (wm + mi*16 + g)*GROWB + kbyte;
                ah[mi][0] = *(const uint32_t*)(p);
                ah[mi][1] = *(const uint32_t*)(p + 8*GROWB);
                ah[mi][2] = *(const uint32_t*)(p + 16);
                ah[mi][3] = *(const uint32_t*)(p + 8*GROWB + 16);
            }
            #pragma unroll
            for (int ni = 0; ni < 8; ni++) {
                const char* p = sm + GARR + (wn + ni*8 + g)*GROWB + kbyte;
                bb[ni][0] = *(const uint32_t*)(p);
                bb[ni][1] = *(const uint32_t*)(p + 16);
            }
            #pragma unroll
            for (int mi = 0; mi < 4; mi++)
                #pragma unroll
                for (int ni = 0; ni < 8; ni++)
                    mma_f16(acc[mi][ni], ah[mi], bb[ni]);
        }
    };

    CP_WAIT1();          // K-half 0 resident
    __syncthreads();
    mma_half(0);
    CP_WAIT0();          // K-half 1 resident
    __syncthreads();
    mma_half(4);

    const float* sbias = (const float*)(sm + SM_BIAS);
    #pragma unroll
    for (int mi = 0; mi < 4; mi++)
        #pragma unroll
        for (int h2 = 0; h2 < 2; h2++) {
            int m = m0 + wm + mi*16 + g + h2*8;
            if (m < NND) {
                #pragma unroll
                for (int ni = 0; ni < 8; ni++) {
                    int n = wn + ni*8 + tig*2;
                    __half2 hv;
                    hv.x = __float2half_rn(acc[mi][ni][2*h2]   + sbias[n]);
                    hv.y = __float2half_rn(acc[mi][ni][2*h2+1] + sbias[n+1]);
                    *(uint32_t*)(g_ht + (size_t)m*KCONV + n0 + n) =
                        *reinterpret_cast<uint32_t*>(&hv);
                }
            }
        }
}

// ---------------- BN+ReLU -> fp16 A for layer 2 ----------------
__global__ void bnrelu_k() {
    int i = blockIdx.x*blockDim.x + threadIdx.x;   // float4 index
    const int n4 = NND*FH/4;
    if (i < n4) {
        float4 v = *((const float4*)g_c + i);
        int cb = (i & 31) * 4;
        v.x = fmaxf(v.x * g_coef[cb+0] + g_coef[FH+cb+0], 0.f);
        v.y = fmaxf(v.y * g_coef[cb+1] + g_coef[FH+cb+1], 0.f);
        v.z = fmaxf(v.z * g_coef[cb+2] + g_coef[FH+cb+2], 0.f);
        v.w = fmaxf(v.w * g_coef[cb+3] + g_coef[FH+cb+3], 0.f);
        __half2 h0, h1;
        h0.x = __float2half_rn(v.x); h0.y = __float2half_rn(v.y);
        h1.x = __float2half_rn(v.z); h1.y = __float2half_rn(v.w);
        uint2 hv;
        hv.x = *reinterpret_cast<uint32_t*>(&h0);
        hv.y = *reinterpret_cast<uint32_t*>(&h1);
        *reinterpret_cast<uint2*>(g_xh + (size_t)i*4) = hv;
    }
}

// ---------------- CSR build (dst-keyed) ----------------
__global__ void hist_k(const int* __restrict__ dst) {
    int e = blockIdx.x*blockDim.x + threadIdx.x;
    if (e < EE) atomicAdd(&g_deg[dst[e]], 1);
}
__global__ void scan1_k() {
    __shared__ int s[1024];
    int t = threadIdx.x;
    int i = blockIdx.x*1024 + t;
    int v = (i < NND) ? g_deg[i] : 0;
    s[t] = v; __syncthreads();
    for (int off = 1; off < 1024; off <<= 1) {
        int x = (t >= off) ? s[t-off] : 0;
        __syncthreads(); s[t] += x; __syncthreads();
    }
    if (i < NND) g_tmp[i] = s[t];
    if (t == 1023) g_bsum[blockIdx.x] = s[t];
}
__global__ void scan2_k(int nb) {
    __shared__ int s[512];
    int t = threadIdx.x;
    s[t] = (t < nb) ? g_bsum[t] : 0; __syncthreads();
    for (int off = 1; off < 512; off <<= 1) {
        int x = (t >= off) ? s[t-off] : 0;
        __syncthreads(); s[t] += x; __syncthreads();
    }
    if (t < nb) g_bsum[t] = s[t];
}
__global__ void scan3_k() {
    int i = blockIdx.x*blockDim.x + threadIdx.x;
    if (i < NND) {
        int b = i >> 10;
        int incl = g_tmp[i] + (b > 0 ? g_bsum[b-1] : 0);
        g_rowptr[i+1] = incl;
        g_cursor[i]   = incl - g_deg[i];
        if (i == 0) g_rowptr[0] = 0;
    }
}
__global__ void scatter_k(const int* __restrict__ src, const int* __restrict__ dst,
                          const int* __restrict__ et) {
    int e = blockIdx.x*blockDim.x + threadIdx.x;
    if (e < EE) {
        int pos = atomicAdd(&g_cursor[dst[e]], 1);
        g_enc[pos] = src[e]*NCH + et[e];
    }
}

// ---------------- gather + bias + fused BN stats (MLP-8 edge loop) ----------------
__global__ void __launch_bounds__(256)
gatherT_k(const float* __restrict__ bias) {
    __shared__ float ss[FH], sq[FH];
    int t = threadIdx.x, lane = t & 31;
    if (t < FH) { ss[t] = 0.f; sq[t] = 0.f; }
    __syncthreads();

    int w = (blockIdx.x*blockDim.x + t) >> 5;   // one warp per node
    if (w < NND) {
        int beg = g_rowptr[w], end = g_rowptr[w+1];
        const uint2* htp = (const uint2*)g_ht;

        float4 acc = h4f4(htp[(size_t)(w*NCH + 8)*32 + lane]);  // root/self
        int e = beg;
        for (; e + 8 <= end; e += 8) {
            uint2 v[8];
            #pragma unroll
            for (int q = 0; q < 8; q++) v[q] = htp[(size_t)g_enc[e+q]*32 + lane];
            #pragma unroll
            for (int q = 0; q < 8; q++) {
                float4 f = h4f4(v[q]);
                acc.x += f.x; acc.y += f.y; acc.z += f.z; acc.w += f.w;
            }
        }
        for (; e < end; e++) {
            float4 f = h4f4(htp[(size_t)g_enc[e]*32 + lane]);
            acc.x += f.x; acc.y += f.y; acc.z += f.z; acc.w += f.w;
        }
        float4 b = *((const float4*)bias + lane);
        acc.x += b.x; acc.y += b.y; acc.z += b.z; acc.w += b.w;
        *((float4*)(g_c + (size_t)w*FH) + lane) = acc;

        int cb = lane*4;
        atomicAdd(&ss[cb+0], acc.x); atomicAdd(&sq[cb+0], acc.x*acc.x);
        atomicAdd(&ss[cb+1], acc.y); atomicAdd(&sq[cb+1], acc.y*acc.y);
        atomicAdd(&ss[cb+2], acc.z); atomicAdd(&sq[cb+2], acc.z*acc.z);
        atomicAdd(&ss[cb+3], acc.w); atomicAdd(&sq[cb+3], acc.w*acc.w);
    }
    __syncthreads();
    if (t < FH) {
        atomicAdd(&g_colsum[t], ss[t]);
        atomicAdd(&g_colsq[t],  sq[t]);
    }
}

// ---------------- BN coef (reads stats, then resets them for the next layer) ----------------
__global__ void bncoef_k(const float* __restrict__ gamma, const float* __restrict__ beta) {
    int c = threadIdx.x;
    float mu  = g_colsum[c] / (float)NND;
    float var = g_colsq[c] / (float)NND - mu*mu;
    float sc  = gamma[c] * rsqrtf(var + BN_EPS);
    g_coef[c]      = sc;
    g_coef[FH + c] = beta[c] - mu * sc;
    g_colsum[c] = 0.f;
    g_colsq[c]  = 0.f;
}

// ---------------- head ----------------
__global__ void w2o_k(const float* __restrict__ W2, const float* __restrict__ b2,
                      const float* __restrict__ Wo, const float* __restrict__ bo) {
    int c = threadIdx.x;
    float s = 0.f;
    for (int j = 0; j < FH; j++) s += W2[c*FH + j] * Wo[j];
    g_w2o[c] = s;
    if (c == 0) {
        float b = bo[0];
        for (int j = 0; j < FH; j++) b += b2[j] * Wo[j];
        g_w2o[FH] = b;
    }
}
__global__ void head_k(float* __restrict__ out) {
    int w    = (blockIdx.x*blockDim.x + threadIdx.x) >> 5;
    int lane = threadIdx.x & 31;
    if (w >= NND) return;
    float4 v  = *((const float4*)(g_c + (size_t)w*FH) + lane);
    int cb = lane*4;
    v.x = fmaxf(v.x * g_coef[cb+0] + g_coef[FH+cb+0], 0.f);
    v.y = fmaxf(v.y * g_coef[cb+1] + g_coef[FH+cb+1], 0.f);
    v.z = fmaxf(v.z * g_coef[cb+2] + g_coef[FH+cb+2], 0.f);
    v.w = fmaxf(v.w * g_coef[cb+3] + g_coef[FH+cb+3], 0.f);
    float4 wv = *((const float4*)g_w2o + lane);
    float d = v.x*wv.x + v.y*wv.y + v.z*wv.z + v.w*wv.w;
    #pragma unroll
    for (int off = 16; off; off >>= 1) d += __shfl_down_sync(0xFFFFFFFFu, d, off);
    if (lane == 0) out[w] = 1.f / (1.f + expf(-(d + g_w2o[FH])));
}

// ---------------- launch ----------------
extern "C" void kernel_launch(void* const* d_in, const int* in_sizes, int n_in,
                              void* d_out, int out_size)
{
    const float* x      = (const float*)d_in[0];
    const int*   ei     = (const int*)  d_in[1];
    const int*   et     = (const int*)  d_in[2];
    const float* W1     = (const float*)d_in[3];
    const float* b1     = (const float*)d_in[4];
    const float* weight = (const float*)d_in[5];
    const float* root   = (const float*)d_in[6];
    const float* bias_c = (const float*)d_in[7];
    const float* gamma  = (const float*)d_in[8];
    const float* beta   = (const float*)d_in[9];
    const float* W2     = (const float*)d_in[10];
    const float* b2     = (const float*)d_in[11];
    const float* Wo     = (const float*)d_in[12];
    const float* bo     = (const float*)d_in[13];
    float* out = (float*)d_out;

    __half *xHP, *BcP, *B1cP;
    float *bc1P;
    cudaGetSymbolAddress((void**)&xHP,  g_xh);
    cudaGetSymbolAddress((void**)&BcP,  g_Bc);
    cudaGetSymbolAddress((void**)&B1cP, g_B1c);
    cudaGetSymbolAddress((void**)&bc1P, g_bc1);

    cudaFuncSetAttribute(gemmT_k, cudaFuncAttributeMaxDynamicSharedMemorySize, SMEM_G);

    const int T = 256;
    const int nScan1 = (NND + 1023) / 1024;   // 49
    const int mTiles = (NND + 127) / 128;     // 391

    // launches ordered so gemmT (layer 1) is our 4th kernel -> captured by ncu -s 5
    prepX_k<<<(NND*FH + T-1)/T, T>>>(x);
    prepB_k<<<(KCONV*FH + T-1)/T, T>>>(weight, root);
    prepB1c_k<<<(FH*KCONV + T-1)/T, T>>>(W1, b1, weight, root);
    gemmT_k<<<dim3(mTiles, NCH), 128, SMEM_G>>>(xHP, B1cP, bc1P);   // layer-1 (folded)

    // CSR build (dst-keyed)
    hist_k<<<(EE + T-1)/T, T>>>(ei + EE);
    scan1_k<<<nScan1, 1024>>>();
    scan2_k<<<1, 512>>>(nScan1);
    scan3_k<<<(NND + T-1)/T, T>>>();
    scatter_k<<<(EE + T-1)/T, T>>>(ei, ei + EE, et);

    w2o_k<<<1, FH>>>(W2, b2, Wo, bo);

    // layer 1: gather + stats -> coef (bncoef resets stats)
    gatherT_k<<<(NND*32 + T-1)/T, T>>>(bias_c);
    bncoef_k<<<1, FH>>>(gamma, beta);

    // layer 2: BN+ReLU -> fp16 A, then transform -> gather + stats -> coef
    bnrelu_k<<<(NND*FH/4 + T-1)/T, T>>>();
    gemmT_k<<<dim3(mTiles, NCH), 128, SMEM_G>>>(xHP, BcP, nullptr);
    gatherT_k<<<(NND*32 + T-1)/T, T>>>(bias_c);
    bncoef_k<<<1, FH>>>(gamma, beta);

    // head (fused BN+ReLU + dot + sigmoid)
    head_k<<<(NND*32 + T-1)/T, T>>>(out);
}